// round 2
// baseline (speedup 1.0000x reference)
#include <cuda_runtime.h>

#define BM 128
#define BN 128
#define BK 16
#define NTHREADS 256

// ---------------------------------------------------------------------------
// KAN inner activation: inner = c0*B0(tanh(x)) + c1*B1(tanh(x))
// Cubic (order-3) Cox-de Boor on uniform knots linspace(-1,1,8), n_active=2.
// ---------------------------------------------------------------------------
__device__ __forceinline__ float kan_act(float xv, float c0, float c1) {
    // accurate-enough tanh independent of fast-math flags:
    // tanh(x) = 1 - 2/(exp(2x)+1);  abs err ~1e-6, spline is C2 so fine.
    float e = __expf(2.0f * xv);
    float t = 1.0f - __fdividef(2.0f, e + 1.0f);

    const float K0 = -1.0f;
    const float K1 = (float)(-1.0 + 1.0 * (2.0 / 7.0));
    const float K2 = (float)(-1.0 + 2.0 * (2.0 / 7.0));
    const float K3 = (float)(-1.0 + 3.0 * (2.0 / 7.0));
    const float K4 = (float)(-1.0 + 4.0 * (2.0 / 7.0));
    const float K5 = (float)(-1.0 + 5.0 * (2.0 / 7.0));
    const float I1 = 3.5f;                  // 1/h,  h = 2/7
    const float I2 = 1.75f;                 // 1/(2h)
    const float I3 = (float)(7.0 / 6.0);    // 1/(3h)

    // order 0 indicators (half-open intervals, matching reference)
    float b00 = (t >= K0 && t < K1) ? 1.0f : 0.0f;
    float b01 = (t >= K1 && t < K2) ? 1.0f : 0.0f;
    float b02 = (t >= K2 && t < K3) ? 1.0f : 0.0f;
    float b03 = (t >= K3 && t < K4) ? 1.0f : 0.0f;
    float b04 = (t >= K4 && t < K5) ? 1.0f : 0.0f;
    // order 1
    float b10 = ((t - K0) * b00 + (K2 - t) * b01) * I1;
    float b11 = ((t - K1) * b01 + (K3 - t) * b02) * I1;
    float b12 = ((t - K2) * b02 + (K4 - t) * b03) * I1;
    float b13 = ((t - K3) * b03 + (K5 - t) * b04) * I1;
    // order 2
    float b20 = ((t - K0) * b10 + (K3 - t) * b11) * I2;
    float b21 = ((t - K1) * b11 + (K4 - t) * b12) * I2;
    float b22 = ((t - K2) * b12 + (K5 - t) * b13) * I2;
    // order 3 (only k=0,1 are active)
    float b30 = ((t - K0) * b20 + (K4 - t) * b21) * I3;
    float b31 = ((t - K1) * b21 + (K5 - t) * b22) * I3;

    return c0 * b30 + c1 * b31;
}

// ---------------------------------------------------------------------------
// Fused kernel: C[m,n] = sum_k kan_act(x[m,k]; ic[k]) * W[n,k]
// Classic SGEMM tiling, activation fused into the A-tile global load.
// ---------------------------------------------------------------------------
__global__ void __launch_bounds__(NTHREADS, 2)
kan_fused_sgemm(const float* __restrict__ x,
                const float* __restrict__ ic,   // [256,5] inner coeffs
                const float* __restrict__ oc,   // [N,256] outer coeffs
                float* __restrict__ out,
                int K_dim)                      // = 256
{
    __shared__ float As[BK][BM];
    __shared__ float Bs[BK][BN];
    __shared__ float c0s[256];
    __shared__ float c1s[256];

    const int tid = threadIdx.x;
    const int m0 = blockIdx.y * BM;
    const int n0 = blockIdx.x * BN;

    // stage inner coeffs (only first 2 of 5 columns are active)
    c0s[tid] = ic[tid * 5 + 0];
    c1s[tid] = ic[tid * 5 + 1];
    __syncthreads();

    const int ty = tid >> 4;   // 0..15  -> M fragment
    const int tx = tid & 15;   // 0..15  -> N fragment

    float acc[8][8];
#pragma unroll
    for (int i = 0; i < 8; i++)
#pragma unroll
        for (int j = 0; j < 8; j++) acc[i][j] = 0.0f;

    for (int kt = 0; kt < K_dim; kt += BK) {
        // ---- load + activate A tile: As[k][m] = act(x[m0+m, kt+k]) ----
#pragma unroll
        for (int l = 0; l < 2; l++) {
            int idx = tid + l * NTHREADS;
            int row = idx >> 2;        // 0..127
            int c4  = idx & 3;         // 0..3
            const float4 xv = *reinterpret_cast<const float4*>(
                &x[(size_t)(m0 + row) * K_dim + kt + c4 * 4]);
            int kb = kt + c4 * 4;
            As[c4 * 4 + 0][row] = kan_act(xv.x, c0s[kb + 0], c1s[kb + 0]);
            As[c4 * 4 + 1][row] = kan_act(xv.y, c0s[kb + 1], c1s[kb + 1]);
            As[c4 * 4 + 2][row] = kan_act(xv.z, c0s[kb + 2], c1s[kb + 2]);
            As[c4 * 4 + 3][row] = kan_act(xv.w, c0s[kb + 3], c1s[kb + 3]);
        }
        // ---- load B tile: Bs[k][n] = W[n0+n, kt+k] ----
#pragma unroll
        for (int l = 0; l < 2; l++) {
            int idx = tid + l * NTHREADS;
            int row = idx >> 2;
            int c4  = idx & 3;
            const float4 wv = *reinterpret_cast<const float4*>(
                &oc[(size_t)(n0 + row) * K_dim + kt + c4 * 4]);
            Bs[c4 * 4 + 0][row] = wv.x;
            Bs[c4 * 4 + 1][row] = wv.y;
            Bs[c4 * 4 + 2][row] = wv.z;
            Bs[c4 * 4 + 3][row] = wv.w;
        }
        __syncthreads();

#pragma unroll
        for (int kk = 0; kk < BK; kk++) {
            float4 a0 = *reinterpret_cast<const float4*>(&As[kk][ty * 8 + 0]);
            float4 a1 = *reinterpret_cast<const float4*>(&As[kk][ty * 8 + 4]);
            float4 b0 = *reinterpret_cast<const float4*>(&Bs[kk][tx * 8 + 0]);
            float4 b1 = *reinterpret_cast<const float4*>(&Bs[kk][tx * 8 + 4]);
            float a[8] = {a0.x, a0.y, a0.z, a0.w, a1.x, a1.y, a1.z, a1.w};
            float b[8] = {b0.x, b0.y, b0.z, b0.w, b1.x, b1.y, b1.z, b1.w};
#pragma unroll
            for (int i = 0; i < 8; i++)
#pragma unroll
                for (int j = 0; j < 8; j++)
                    acc[i][j] = fmaf(a[i], b[j], acc[i][j]);
        }
        __syncthreads();
    }

    // ---- epilogue: coalesced float4 stores ----
#pragma unroll
    for (int i = 0; i < 8; i++) {
        size_t off = (size_t)(m0 + ty * 8 + i) * (size_t)(gridDim.x * BN) + n0 + tx * 8;
        float4 v0 = make_float4(acc[i][0], acc[i][1], acc[i][2], acc[i][3]);
        float4 v1 = make_float4(acc[i][4], acc[i][5], acc[i][6], acc[i][7]);
        *reinterpret_cast<float4*>(&out[off + 0]) = v0;
        *reinterpret_cast<float4*>(&out[off + 4]) = v1;
    }
}

extern "C" void kernel_launch(void* const* d_in, const int* in_sizes, int n_in,
                              void* d_out, int out_size) {
    const float* x  = (const float*)d_in[0];  // [B,S,IN] fp32
    const float* ic = (const float*)d_in[1];  // [IN,5]  fp32
    const float* oc = (const float*)d_in[2];  // [OUT,IN] fp32
    float* out = (float*)d_out;

    const int IN  = 256;
    const int M   = in_sizes[0] / IN;   // 65536
    const int OUT = in_sizes[2] / IN;   // 256

    dim3 grid(OUT / BN, M / BM);        // (2, 512)
    kan_fused_sgemm<<<grid, NTHREADS>>>(x, ic, oc, out, IN);
}